// round 1
// baseline (speedup 1.0000x reference)
#include <cuda_runtime.h>
#include <math.h>
#include <stdint.h>

#define NN  50000
#define NE  800000
#define DD  256
#define NET 3
#define NSTEPS 5
#define NGR 64
#define G3  768   // 3*D

// ---------------- device scratch (no allocation allowed) ----------------
__device__ float g_h0[NN * DD];
__device__ float g_h1[NN * DD];
__device__ float g_acc[NET][NN * DD];   // per-etype aggregated h[src]
__device__ int   g_cnt[NET][NN];        // per-etype in-degree (for bias term)
__device__ float g_a [NN * DD];         // message aggregate after GEMM
__device__ float g_gi[NN * G3];
__device__ float g_gh[NN * G3];
__device__ float g_gate[NN];

// ---------------- helpers ----------------
__device__ __forceinline__ void red4(float* p, float4 v) {
    asm volatile("red.global.add.v4.f32 [%0], {%1,%2,%3,%4};"
                 :: "l"(p), "f"(v.x), "f"(v.y), "f"(v.z), "f"(v.w) : "memory");
}

__device__ __forceinline__ float sigmoidf_(float x) { return 1.0f / (1.0f + expf(-x)); }

// ---------------- init: h = emb[x] ----------------
__global__ void embed_kernel(const int* __restrict__ x, const float* __restrict__ emb,
                             float* __restrict__ h) {
    int i = blockIdx.x * blockDim.x + threadIdx.x;          // over NN*DD/4
    const int nf4 = DD / 4;
    if (i >= NN * nf4) return;
    int n = i / nf4, d4 = i - n * nf4;
    int row = x[n];
    ((float4*)h)[i] = ((const float4*)(emb + (size_t)row * DD))[d4];
}

// ---------------- zero acc + cnt ----------------
__global__ void zero_kernel() {
    int i = blockIdx.x * blockDim.x + threadIdx.x;
    const int TOT4 = NET * NN * DD / 4;                     // 9.6M float4
    if (i < TOT4) ((float4*)g_acc)[i] = make_float4(0.f, 0.f, 0.f, 0.f);
    if (i < NET * NN) ((int*)g_cnt)[i] = 0;
}

// ---------------- edge scatter: acc[et][dst] += h[src]; cnt[et][dst]++ ----
__global__ void edge_scatter(const int* __restrict__ src, const int* __restrict__ dst,
                             const int* __restrict__ et, const float* __restrict__ h) {
    int w = (blockIdx.x * blockDim.x + threadIdx.x) >> 5;
    int lane = threadIdx.x & 31;
    if (w >= NE) return;
    int s = __ldg(src + w), d = __ldg(dst + w), t = __ldg(et + w);
    const float4* hs = (const float4*)(h + (size_t)s * DD);
    float* out = &g_acc[t][(size_t)d * DD];
#pragma unroll
    for (int i = 0; i < 2; i++) {
        int c = lane + 32 * i;          // 0..63 float4 per row
        float4 v = hs[c];
        red4(out + 4 * c, v);
    }
    if (lane == 0) atomicAdd(&g_cnt[t][d], 1);
}

// ---------------- SGEMM core: 128x128x16 tile, 8x8 microtile ----------------
#define BM 128
#define BN 128
#define BK 16
#define PAD 4

// load [128 rows x 16 cols] tile of row-major G (ld = 256), store k-major transposed
__device__ __forceinline__ void load_T(float S[BK][BM + PAD], const float* __restrict__ G,
                                       int rowbase, int kc, int rowmax, int tid) {
#pragma unroll
    for (int q = tid; q < 512; q += 256) {
        int r = q >> 2;                 // 0..127
        int cg = (q & 3) << 2;          // 0,4,8,12
        int row = rowbase + r;
        float4 v = make_float4(0.f, 0.f, 0.f, 0.f);
        if (row < rowmax) v = *(const float4*)(G + (size_t)row * DD + kc + cg);
        S[cg + 0][r] = v.x; S[cg + 1][r] = v.y; S[cg + 2][r] = v.z; S[cg + 3][r] = v.w;
    }
}

// load [16 rows x 128 cols] of row-major B (rows are K), direct layout
__device__ __forceinline__ void load_B(float S[BK][BM + PAD], const float* __restrict__ G,
                                       int ld, int kc, int colbase, int tid) {
#pragma unroll
    for (int q = tid; q < 512; q += 256) {
        int k = q >> 5;                 // 0..15
        int c = (q & 31) << 2;          // 0..124
        float4 v = *(const float4*)(G + (size_t)(kc + k) * ld + colbase + c);
        *(float4*)&S[k][c] = v;
    }
}

__device__ __forceinline__ void mac16(float acc[8][8],
                                      const float As[BK][BM + PAD],
                                      const float Bs[BK][BM + PAD], int ty, int tx) {
#pragma unroll
    for (int k = 0; k < BK; k++) {
        float a[8], b[8];
        *(float4*)(a)     = *(const float4*)&As[k][ty * 8];
        *(float4*)(a + 4) = *(const float4*)&As[k][ty * 8 + 4];
        *(float4*)(b)     = *(const float4*)&Bs[k][tx * 8];
        *(float4*)(b + 4) = *(const float4*)&Bs[k][tx * 8 + 4];
#pragma unroll
        for (int i = 0; i < 8; i++)
#pragma unroll
            for (int j = 0; j < 8; j++) acc[i][j] += a[i] * b[j];
    }
}

// a = sum_et acc_et @ W_et  +  sum_et cnt_et * b_msg_et   (writes g_a)
__global__ void __launch_bounds__(256, 2)
gemm_msg(const float* __restrict__ Wmsg, const float* __restrict__ bmsg) {
    __shared__ float As[BK][BM + PAD];
    __shared__ float Bs[BK][BM + PAD];
    int tid = threadIdx.x, tx = tid & 15, ty = tid >> 4;
    int row0 = blockIdx.x * BM, col0 = blockIdx.y * BN;
    float acc[8][8];
#pragma unroll
    for (int i = 0; i < 8; i++)
#pragma unroll
        for (int j = 0; j < 8; j++) acc[i][j] = 0.f;

    for (int e = 0; e < NET; e++) {
        const float* A = g_acc[e];
        const float* B = Wmsg + (size_t)e * DD * DD;
        for (int kc = 0; kc < DD; kc += BK) {
            __syncthreads();
            load_T(As, A, row0, kc, NN, tid);
            load_B(Bs, B, DD, kc, col0, tid);
            __syncthreads();
            mac16(acc, As, Bs, ty, tx);
        }
    }
    // epilogue: + cnt[et][row] * b_msg[et][col]
    float bm[NET][8];
#pragma unroll
    for (int e = 0; e < NET; e++)
#pragma unroll
        for (int j = 0; j < 8; j++) bm[e][j] = bmsg[e * DD + col0 + tx * 8 + j];

#pragma unroll
    for (int i = 0; i < 8; i++) {
        int r = row0 + ty * 8 + i;
        if (r >= NN) break;
        float c0 = (float)g_cnt[0][r], c1 = (float)g_cnt[1][r], c2 = (float)g_cnt[2][r];
        float o[8];
#pragma unroll
        for (int j = 0; j < 8; j++)
            o[j] = acc[i][j] + c0 * bm[0][j] + c1 * bm[1][j] + c2 * bm[2][j];
        float* cp = g_a + (size_t)r * DD + col0 + tx * 8;
        *(float4*)(cp)     = *(float4*)(o);
        *(float4*)(cp + 4) = *(float4*)(o + 4);
    }
}

// C[n,j] = sum_k A[n,k] * Bt[j,k] + bias[j]   (Bt row-major [ncols,256])
__global__ void __launch_bounds__(256, 2)
gemm_bt(const float* __restrict__ A, const float* __restrict__ Bt,
        const float* __restrict__ bias, float* __restrict__ C, int ncols) {
    __shared__ float As[BK][BM + PAD];
    __shared__ float Bs[BK][BM + PAD];
    int tid = threadIdx.x, tx = tid & 15, ty = tid >> 4;
    int row0 = blockIdx.x * BM, col0 = blockIdx.y * BN;
    float acc[8][8];
#pragma unroll
    for (int i = 0; i < 8; i++)
#pragma unroll
        for (int j = 0; j < 8; j++) acc[i][j] = 0.f;

    for (int kc = 0; kc < DD; kc += BK) {
        __syncthreads();
        load_T(As, A, row0, kc, NN, tid);
        load_T(Bs, Bt, col0, kc, ncols, tid);   // transpose-on-load of Bt
        __syncthreads();
        mac16(acc, As, Bs, ty, tx);
    }
    float bv[8];
#pragma unroll
    for (int j = 0; j < 8; j++) bv[j] = bias[col0 + tx * 8 + j];
#pragma unroll
    for (int i = 0; i < 8; i++) {
        int r = row0 + ty * 8 + i;
        if (r >= NN) break;
        float o[8];
#pragma unroll
        for (int j = 0; j < 8; j++) o[j] = acc[i][j] + bv[j];
        float* cp = C + (size_t)r * ncols + col0 + tx * 8;
        *(float4*)(cp)     = *(float4*)(o);
        *(float4*)(cp + 4) = *(float4*)(o + 4);
    }
}

// ---------------- GRU gates (elementwise) ----------------
__global__ void gru_gate(const float* __restrict__ gi, const float* __restrict__ gh,
                         const float* __restrict__ h, float* __restrict__ hnew) {
    int i = blockIdx.x * blockDim.x + threadIdx.x;   // over NN*DD/4
    const int nf4 = DD / 4;
    if (i >= NN * nf4) return;
    int n = i / nf4, d4 = i - n * nf4;
    const float4* GI4 = (const float4*)(gi + (size_t)n * G3);
    const float4* GH4 = (const float4*)(gh + (size_t)n * G3);
    float4 ir = GI4[d4], iz = GI4[64 + d4], in_ = GI4[128 + d4];
    float4 hr = GH4[d4], hz = GH4[64 + d4], hn = GH4[128 + d4];
    float4 hv = ((const float4*)h)[i];
    float4 o;
    {
        float r = sigmoidf_(ir.x + hr.x), z = sigmoidf_(iz.x + hz.x);
        float nn = tanhf(in_.x + r * hn.x); o.x = (1.f - z) * nn + z * hv.x;
    }
    {
        float r = sigmoidf_(ir.y + hr.y), z = sigmoidf_(iz.y + hz.y);
        float nn = tanhf(in_.y + r * hn.y); o.y = (1.f - z) * nn + z * hv.y;
    }
    {
        float r = sigmoidf_(ir.z + hr.z), z = sigmoidf_(iz.z + hz.z);
        float nn = tanhf(in_.z + r * hn.z); o.z = (1.f - z) * nn + z * hv.z;
    }
    {
        float r = sigmoidf_(ir.w + hr.w), z = sigmoidf_(iz.w + hz.w);
        float nn = tanhf(in_.w + r * hn.w); o.w = (1.f - z) * nn + z * hv.w;
    }
    ((float4*)hnew)[i] = o;
}

// ---------------- gate score: gate[n] = h[n,:] . gate_w + gate_b ----------
__global__ void gate_kernel(const float* __restrict__ h, const float* __restrict__ gw,
                            const float* __restrict__ gb) {
    int w = (blockIdx.x * blockDim.x + threadIdx.x) >> 5;
    int lane = threadIdx.x & 31;
    if (w >= NN) return;
    float s = 0.f;
    const float* hr = h + (size_t)w * DD;
#pragma unroll
    for (int d = lane; d < DD; d += 32) s += hr[d] * gw[d];
#pragma unroll
    for (int o = 16; o; o >>= 1) s += __shfl_xor_sync(0xffffffffu, s, o);
    if (lane == 0) g_gate[w] = s + gb[0];
}

// ---------------- segment softmax + weighted pool (block per graph) -------
__device__ __forceinline__ int lb_(const int* a, int n, int v) {
    int lo = 0, hi = n;
    while (lo < hi) { int m = (lo + hi) >> 1; if (a[m] < v) lo = m + 1; else hi = m; }
    return lo;
}

__global__ void pool_kernel(const float* __restrict__ h, const int* __restrict__ seg,
                            float* __restrict__ out) {
    __shared__ float red[256];
    __shared__ float s_scalar;
    int g = blockIdx.x, tid = threadIdx.x;
    int s = lb_(seg, NN, g), e = lb_(seg, NN, g + 1);

    // max
    float m = -INFINITY;
    for (int i = s + tid; i < e; i += 256) m = fmaxf(m, g_gate[i]);
    red[tid] = m; __syncthreads();
    for (int o = 128; o; o >>= 1) { if (tid < o) red[tid] = fmaxf(red[tid], red[tid + o]); __syncthreads(); }
    if (tid == 0) s_scalar = red[0];
    __syncthreads();
    float gm = s_scalar;
    __syncthreads();

    // denom
    float sum = 0.f;
    for (int i = s + tid; i < e; i += 256) sum += expf(g_gate[i] - gm);
    red[tid] = sum; __syncthreads();
    for (int o = 128; o; o >>= 1) { if (tid < o) red[tid] += red[tid + o]; __syncthreads(); }
    if (tid == 0) s_scalar = red[0];
    __syncthreads();
    float denom = s_scalar;
    __syncthreads();

    // weighted sum over nodes, thread = one dim
    float acc = 0.f;
    for (int i0 = s; i0 < e; i0 += 256) {
        int i = i0 + tid;
        red[tid] = (i < e) ? expf(g_gate[i] - gm) : 0.f;
        __syncthreads();
        int lim = min(256, e - i0);
        for (int k = 0; k < lim; k++) acc += h[(size_t)(i0 + k) * DD + tid] * red[k];
        __syncthreads();
    }
    out[g * DD + tid] = (e > s) ? acc / denom : 0.f;
}

// ---------------- launch ----------------
extern "C" void kernel_launch(void* const* d_in, const int* in_sizes, int n_in,
                              void* d_out, int out_size) {
    const int* x   = (const int*)d_in[0];
    const int* src = (const int*)d_in[1];
    const int* dst = (const int*)d_in[2];
    const int* et  = (const int*)d_in[3];
    const int* seg = (const int*)d_in[4];
    int base = (in_sizes[5] == 1) ? 6 : 5;   // skip num_graphs scalar if present
    const float* emb    = (const float*)d_in[base + 0];
    const float* Wmsg   = (const float*)d_in[base + 1];
    const float* bmsg   = (const float*)d_in[base + 2];
    const float* w_ih   = (const float*)d_in[base + 3];
    const float* w_hh   = (const float*)d_in[base + 4];
    const float* b_ih   = (const float*)d_in[base + 5];
    const float* b_hh   = (const float*)d_in[base + 6];
    const float* gate_w = (const float*)d_in[base + 7];
    const float* gate_b = (const float*)d_in[base + 8];
    float* out = (float*)d_out;

    float *ph0, *ph1, *pa, *pgi, *pgh;
    cudaGetSymbolAddress((void**)&ph0, g_h0);
    cudaGetSymbolAddress((void**)&ph1, g_h1);
    cudaGetSymbolAddress((void**)&pa,  g_a);
    cudaGetSymbolAddress((void**)&pgi, g_gi);
    cudaGetSymbolAddress((void**)&pgh, g_gh);

    const int elem4 = NN * DD / 4;                 // 3.2M
    embed_kernel<<<(elem4 + 255) / 256, 256>>>(x, emb, ph0);

    const int rowblk = (NN + BM - 1) / BM;         // 391
    float* hin = ph0;
    float* hout = ph1;
    for (int step = 0; step < NSTEPS; step++) {
        zero_kernel<<<(NET * NN * DD / 4 + 255) / 256, 256>>>();
        edge_scatter<<<(NE * 32 + 255) / 256, 256>>>(src, dst, et, hin);
        gemm_msg<<<dim3(rowblk, DD / BN), 256>>>(Wmsg, bmsg);
        gemm_bt<<<dim3(rowblk, G3 / BN), 256>>>(pa,  w_ih, b_ih, pgi, G3);
        gemm_bt<<<dim3(rowblk, G3 / BN), 256>>>(hin, w_hh, b_hh, pgh, G3);
        gru_gate<<<(elem4 + 255) / 256, 256>>>(pgi, pgh, hin, hout);
        float* t = hin; hin = hout; hout = t;
    }
    // after 5 steps, hin points at the latest h
    gate_kernel<<<(NN * 32 + 255) / 256, 256>>>(hin, gate_w, gate_b);
    pool_kernel<<<NGR, 256>>>(hin, seg, out);
}